// round 15
// baseline (speedup 1.0000x reference)
#include <cuda_runtime.h>

// Problem constants (from reference setup_inputs)
#define BD   8        // batch
#define NN   2048     // N = O*K
#define HH   128      // hidden
#define TT   10       // pred_len
#define MAXN 256      // neighbor cap (avg degree ~10)

// ---------------- device scratch (no allocations allowed) ----------------
__device__ float g_pos[BD * NN * 3];
__device__ float g_vel[BD * NN * 3];
__device__ __align__(16) float g_ha[BD * NN * HH];     // h ping
__device__ __align__(16) float g_hb[BD * NN * HH];     // h pong
__device__ int   g_nbr[BD * NN * MAXN];
__device__ int   g_cnt[BD * NN];
__device__ float g_dinv[BD * NN];

// ---------------- init: pos=points, vel=0, write t=0 output ----------------
__global__ void k_init(const float* __restrict__ pts, float* __restrict__ out) {
    int id = blockIdx.x * blockDim.x + threadIdx.x;   // over B*N*3
    if (id < BD * NN * 3) {
        float v = pts[id];
        g_pos[id] = v;
        g_vel[id] = 0.f;
        int c = id % 3;
        int n = (id / 3) % NN;
        int b = id / (3 * NN);
        out[((size_t)(b * (TT + 1)) * NN + n) * 3 + c] = v;
    }
}

// ---------------- adjacency + fused layer0 h (64-row tiles, 512 thr) --------
// grid (NN/64, BD); 16 warps, warp owns 4 rows.
__global__ __launch_bounds__(512) void k_adj(const float* __restrict__ padding,
                                             const float* __restrict__ W0) {
    __shared__ float px[NN], py[NN], pz[NN], pd[NN];
    __shared__ float W0s[6 * HH];
    __shared__ float sv[64][3];
    __shared__ float sdinv[64];
    int b = blockIdx.y, bN = b * NN;
    int i0 = blockIdx.x * 64;
    int tid = threadIdx.x;
    const float* pos = g_pos + (size_t)bN * 3;
    for (int j = tid; j < NN; j += 512) {
        px[j] = pos[j * 3 + 0];
        py[j] = pos[j * 3 + 1];
        pz[j] = pos[j * 3 + 2];
        pd[j] = padding[bN + j];
    }
    for (int k = tid; k < 6 * HH; k += 512) W0s[k] = W0[k];
    if (tid < 192) sv[tid / 3][tid % 3] = g_vel[(bN + i0 + tid / 3) * 3 + tid % 3];
    __syncthreads();

    int warp = tid >> 5, lane = tid & 31;
    const float R2 = 0.01f;   // float32(0.1*0.1), fp32 compare like the ref
    for (int r = 0; r < 4; r++) {
        int rr = warp * 4 + r;            // row-in-block 0..63
        int i = i0 + rr;
        float xi = px[i], yi = py[i], zi = pz[i];
        bool oki = pd[i] > 0.f;
        int base = (bN + i) * MAXN;
        int cnt = 0;
        #pragma unroll 4
        for (int t = 0; t < NN / 32; t++) {
            int j = t * 32 + lane;
            // separate mul/add rounding — matches XLA's sub/mul/reduce-add
            float dx = __fadd_rn(px[j], -xi);
            float dy = __fadd_rn(py[j], -yi);
            float dz = __fadd_rn(pz[j], -zi);
            float d2 = __fadd_rn(__fadd_rn(__fmul_rn(dx, dx), __fmul_rn(dy, dy)),
                                 __fmul_rn(dz, dz));
            // a_hat = adj + I: diagonal always 1; self at its sorted position
            bool hit = (j == i) || (oki && (pd[j] > 0.f) && (d2 < R2));
            unsigned m = __ballot_sync(0xffffffffu, hit);
            if (hit) {
                int off = cnt + __popc(m & ((1u << lane) - 1u));
                if (off < MAXN) g_nbr[base + off] = j;
            }
            cnt += __popc(m);
        }
        if (cnt > MAXN) cnt = MAXN;
        if (lane == 0) {
            // XLA lowers rsqrt as 1/sqrt (correctly rounded), NOT MUFU.RSQ.
            float di = 1.0f / sqrtf((float)cnt);
            g_cnt[bN + i]  = cnt;
            g_dinv[bN + i] = di;
            sdinv[rr] = di;
        }
    }
    __syncthreads();

    // layer0 h for own rows (ascending-k FMA, pos then vel)
    for (int o = tid; o < 64 * HH; o += 512) {
        int r = o >> 7, col = o & 127;
        float acc = 0.f;
        acc = fmaf(px[i0 + r], W0s[0 * HH + col], acc);
        acc = fmaf(py[i0 + r], W0s[1 * HH + col], acc);
        acc = fmaf(pz[i0 + r], W0s[2 * HH + col], acc);
        acc = fmaf(sv[r][0],   W0s[3 * HH + col], acc);
        acc = fmaf(sv[r][1],   W0s[4 * HH + col], acc);
        acc = fmaf(sv[r][2],   W0s[5 * HH + col], acc);
        g_ha[(size_t)(bN + i0 + r) * HH + col] = __fmul_rn(acc, sdinv[r]);
    }
}

// MLP-4 gather: 4 independent LDG.128 in flight, then ordered adds
// (strictly ascending t — bit-identical to the serial loop).
__device__ __forceinline__ float4 gather_row(const float* __restrict__ hin,
                                             const int* __restrict__ nb,
                                             int cnt, int bN, int lane) {
    float4 a = make_float4(0.f, 0.f, 0.f, 0.f);
    int t = 0;
    for (; t + 4 <= cnt; t += 4) {
        int j0 = nb[t], j1 = nb[t + 1], j2 = nb[t + 2], j3 = nb[t + 3];
        float4 v0 = __ldg((const float4*)(hin + (size_t)(bN + j0) * HH) + lane);
        float4 v1 = __ldg((const float4*)(hin + (size_t)(bN + j1) * HH) + lane);
        float4 v2 = __ldg((const float4*)(hin + (size_t)(bN + j2) * HH) + lane);
        float4 v3 = __ldg((const float4*)(hin + (size_t)(bN + j3) * HH) + lane);
        a.x = __fadd_rn(a.x, v0.x); a.y = __fadd_rn(a.y, v0.y);
        a.z = __fadd_rn(a.z, v0.z); a.w = __fadd_rn(a.w, v0.w);
        a.x = __fadd_rn(a.x, v1.x); a.y = __fadd_rn(a.y, v1.y);
        a.z = __fadd_rn(a.z, v1.z); a.w = __fadd_rn(a.w, v1.w);
        a.x = __fadd_rn(a.x, v2.x); a.y = __fadd_rn(a.y, v2.y);
        a.z = __fadd_rn(a.z, v2.z); a.w = __fadd_rn(a.w, v2.w);
        a.x = __fadd_rn(a.x, v3.x); a.y = __fadd_rn(a.y, v3.y);
        a.z = __fadd_rn(a.z, v3.z); a.w = __fadd_rn(a.w, v3.w);
    }
    for (; t < cnt; t++) {
        float4 v = __ldg((const float4*)(hin + (size_t)(bN + nb[t]) * HH) + lane);
        a.x = __fadd_rn(a.x, v.x); a.y = __fadd_rn(a.y, v.y);
        a.z = __fadd_rn(a.z, v.z); a.w = __fadd_rn(a.w, v.w);
    }
    return a;
}

// ---------------- fused aggregate + dense GEMM, warp-local, 512 thr ---------
// Order: issue W->smem copies, then gather (W fill hides under gather
// latency), THEN the single __syncthreads, then GEMM from smem.
// bias/dinv read straight from global; dinv kept in regs for the epilogue.
// src==0: g_ha -> g_hb ; src==1: g_hb -> g_ha.
__global__ __launch_bounds__(512, 2) void k_aggemm(int src,
                                                   const float* __restrict__ bias,
                                                   const float* __restrict__ W) {
    extern __shared__ __align__(16) float sm[];
    float* Ws = sm;                  // 128*128
    float* xs = sm + HH * HH;        // 64*132 (float4-aligned pitch)

    const float* hin  = src ? g_hb : g_ha;
    float*       hout = src ? g_ha : g_hb;

    int row0 = blockIdx.x * 64;
    int tid = threadIdx.x;
    int bN = (row0 / NN) * NN;       // neighbors are batch-local ids
    int warp = tid >> 5, lane = tid & 31;
    int rbase = warp * 4;

    // Issue W fill first: 4096 float4, 8 per thread. Completes under gather.
    #pragma unroll
    for (int k = 0; k < 8; k++) {
        int idx = tid + k * 512;
        ((float4*)Ws)[idx] = __ldg((const float4*)W + idx);
    }

    // Phase A (warp-local): gather own 4 rows into xs; no block sync needed.
    float4 bb = __ldg((const float4*)bias + lane);
    float dloc[4];
    #pragma unroll 1
    for (int rr = 0; rr < 4; rr++) {
        int r = rbase + rr;
        int i = row0 + r;
        float4 a = gather_row(hin, g_nbr + (size_t)i * MAXN, g_cnt[i], bN, lane);
        float di = g_dinv[i];
        dloc[rr] = di;
        float4 o;
        o.x = fmaxf(__fadd_rn(__fmul_rn(a.x, di), bb.x), 0.f);
        o.y = fmaxf(__fadd_rn(__fmul_rn(a.y, di), bb.y), 0.f);
        o.z = fmaxf(__fadd_rn(__fmul_rn(a.z, di), bb.z), 0.f);
        o.w = fmaxf(__fadd_rn(__fmul_rn(a.w, di), bb.w), 0.f);
        *(float4*)&xs[r * 132 + lane * 4] = o;
    }
    __syncthreads();                 // W + all xs ready

    // Phase B (warp-local): rows rbase..rbase+3, cols lane*4..lane*4+3.
    // k strictly ascending per accumulator — bit-identical chain.
    const float* y = xs + rbase * 132;
    float acc[4][4];
    #pragma unroll
    for (int m = 0; m < 4; m++)
        #pragma unroll
        for (int n = 0; n < 4; n++) acc[m][n] = 0.f;

    #pragma unroll 1
    for (int k0 = 0; k0 < HH; k0 += 4) {
        float4 yv0 = *(const float4*)&y[k0];
        float4 yv1 = *(const float4*)&y[132 + k0];
        float4 yv2 = *(const float4*)&y[264 + k0];
        float4 yv3 = *(const float4*)&y[396 + k0];
        #pragma unroll
        for (int kk = 0; kk < 4; kk++) {
            float4 w = *(const float4*)&Ws[(k0 + kk) * HH + lane * 4];
            float y0 = (kk == 0) ? yv0.x : (kk == 1) ? yv0.y : (kk == 2) ? yv0.z : yv0.w;
            float y1 = (kk == 0) ? yv1.x : (kk == 1) ? yv1.y : (kk == 2) ? yv1.z : yv1.w;
            float y2 = (kk == 0) ? yv2.x : (kk == 1) ? yv2.y : (kk == 2) ? yv2.z : yv2.w;
            float y3 = (kk == 0) ? yv3.x : (kk == 1) ? yv3.y : (kk == 2) ? yv3.z : yv3.w;
            acc[0][0] = fmaf(y0, w.x, acc[0][0]); acc[0][1] = fmaf(y0, w.y, acc[0][1]);
            acc[0][2] = fmaf(y0, w.z, acc[0][2]); acc[0][3] = fmaf(y0, w.w, acc[0][3]);
            acc[1][0] = fmaf(y1, w.x, acc[1][0]); acc[1][1] = fmaf(y1, w.y, acc[1][1]);
            acc[1][2] = fmaf(y1, w.z, acc[1][2]); acc[1][3] = fmaf(y1, w.w, acc[1][3]);
            acc[2][0] = fmaf(y2, w.x, acc[2][0]); acc[2][1] = fmaf(y2, w.y, acc[2][1]);
            acc[2][2] = fmaf(y2, w.z, acc[2][2]); acc[2][3] = fmaf(y2, w.w, acc[2][3]);
            acc[3][0] = fmaf(y3, w.x, acc[3][0]); acc[3][1] = fmaf(y3, w.y, acc[3][1]);
            acc[3][2] = fmaf(y3, w.z, acc[3][2]); acc[3][3] = fmaf(y3, w.w, acc[3][3]);
        }
    }

    #pragma unroll
    for (int m = 0; m < 4; m++) {
        int r = rbase + m;
        float d = dloc[m];
        float4 o;
        o.x = __fmul_rn(acc[m][0], d);
        o.y = __fmul_rn(acc[m][1], d);
        o.z = __fmul_rn(acc[m][2], d);
        o.w = __fmul_rn(acc[m][3], d);
        *(float4*)&hout[(size_t)(row0 + r) * HH + lane * 4] = o;
    }
}

// ---------------- fused aggregate + fc head + state update, warp-local -----
// Same reorder: issue Wfc fill, gather, sync, fc. Reads g_ha.
__global__ __launch_bounds__(512) void k_aggfc(const float* __restrict__ bias2,
                                               const float* __restrict__ Wfc,
                                               const float* __restrict__ bfc,
                                               const float* __restrict__ padding,
                                               float* __restrict__ out, int t) {
    __shared__ __align__(16) float xs[64 * 132];
    __shared__ float Wf[HH * 6];
    int row0 = blockIdx.x * 64;
    int tid = threadIdx.x;
    int bN = (row0 / NN) * NN;
    int warp = tid >> 5, lane = tid & 31;
    int rbase = warp * 4;

    // Issue Wfc fill (768 floats) first; completes under gather.
    for (int k = tid; k < HH * 6; k += 512) Wf[k] = __ldg(Wfc + k);

    float4 bb = __ldg((const float4*)bias2 + lane);
    #pragma unroll 1
    for (int rr = 0; rr < 4; rr++) {
        int r = rbase + rr;
        int i = row0 + r;
        float4 a = gather_row(g_ha, g_nbr + (size_t)i * MAXN, g_cnt[i], bN, lane);
        float di = g_dinv[i];
        float4 o;
        o.x = fmaxf(__fadd_rn(__fmul_rn(a.x, di), bb.x), 0.f);
        o.y = fmaxf(__fadd_rn(__fmul_rn(a.y, di), bb.y), 0.f);
        o.z = fmaxf(__fadd_rn(__fmul_rn(a.z, di), bb.z), 0.f);
        o.w = fmaxf(__fadd_rn(__fmul_rn(a.w, di), bb.w), 0.f);
        *(float4*)&xs[r * 132 + lane * 4] = o;
    }
    __syncthreads();

    // fc for own 4 rows: 24 outputs per warp (lanes 0..23).
    if (lane < 24) {
        int rr = lane / 6, c = lane % 6;
        int g = row0 + rbase + rr;
        const float* xr = xs + (rbase + rr) * 132;
        float acc = 0.f;
        #pragma unroll 8
        for (int k = 0; k < HH; k++) acc = fmaf(xr[k], Wf[k * 6 + c], acc);
        float res = __fadd_rn(acc, __ldg(bfc + c));
        res = __fmul_rn(res, padding[g]);
        if (c < 3) {
            float p = __fadd_rn(g_pos[g * 3 + c], res);
            g_pos[g * 3 + c] = p;
            int b = g / NN, n = g % NN;
            out[((size_t)(b * (TT + 1) + t + 1) * NN + n) * 3 + c] = p;
        } else {
            int a = g * 3 + (c - 3);
            g_vel[a] = __fadd_rn(g_vel[a], res);
        }
    }
}

// ---------------- launch ----------------
extern "C" void kernel_launch(void* const* d_in, const int* in_sizes, int n_in,
                              void* d_out, int out_size) {
    const float* points  = (const float*)d_in[0];
    const float* padding = (const float*)d_in[5];
    const float* W0  = (const float*)d_in[6];
    const float* b0  = (const float*)d_in[7];
    const float* W1  = (const float*)d_in[8];
    const float* b1  = (const float*)d_in[9];
    const float* W2  = (const float*)d_in[10];
    const float* b2  = (const float*)d_in[11];
    const float* Wfc = (const float*)d_in[12];
    const float* bfc = (const float*)d_in[13];
    float* out = (float*)d_out;

    const int smem_ag = (HH * HH + 64 * 132) * (int)sizeof(float);
    cudaFuncSetAttribute(k_aggemm, cudaFuncAttributeMaxDynamicSharedMemorySize,
                         smem_ag);

    const int ROWS = BD * NN;

    k_init<<<(BD * NN * 3 + 255) / 256, 256>>>(points, out);

    for (int t = 0; t < TT; t++) {
        k_adj<<<dim3(NN / 64, BD), 512>>>(padding, W0);      // -> g_ha (h0)
        k_aggemm<<<ROWS / 64, 512, smem_ag>>>(0, b0, W1);    // ha -> x -> hb
        k_aggemm<<<ROWS / 64, 512, smem_ag>>>(1, b1, W2);    // hb -> x -> ha
        k_aggfc <<<ROWS / 64, 512>>>(b2, Wfc, bfc, padding, out, t);
    }
}

// round 16
// speedup vs baseline: 1.0560x; 1.0560x over previous
#include <cuda_runtime.h>

// Problem constants (from reference setup_inputs)
#define BD   8        // batch
#define NN   2048     // N = O*K
#define HH   128      // hidden
#define TT   10       // pred_len
#define MAXN 256      // neighbor cap (avg degree ~10)

// ---------------- device scratch (no allocations allowed) ----------------
__device__ float g_pos[BD * NN * 3];
__device__ float g_vel[BD * NN * 3];
__device__ __align__(16) float g_ha[BD * NN * HH];     // h ping
__device__ __align__(16) float g_hb[BD * NN * HH];     // h pong
__device__ int   g_nbr[BD * NN * MAXN];
__device__ int   g_cnt[BD * NN];
__device__ float g_dinv[BD * NN];

// ---------------- init: pos=points, vel=0, write t=0 output ----------------
__global__ void k_init(const float* __restrict__ pts, float* __restrict__ out) {
    int id = blockIdx.x * blockDim.x + threadIdx.x;   // over B*N*3
    if (id < BD * NN * 3) {
        float v = pts[id];
        g_pos[id] = v;
        g_vel[id] = 0.f;
        int c = id % 3;
        int n = (id / 3) % NN;
        int b = id / (3 * NN);
        out[((size_t)(b * (TT + 1)) * NN + n) * 3 + c] = v;
    }
}

// ---------------- adjacency + fused layer0 h (64-row tiles, 512 thr) --------
// t-outer / r-inner scan: one LDS.128 of (x,y,z,pad) per j-chunk serves all
// 4 rows of the warp. Per-row hit logic and t-ascending compaction unchanged
// -> identical neighbor lists / counts.
__global__ __launch_bounds__(512) void k_adj(const float* __restrict__ padding,
                                             const float* __restrict__ W0) {
    __shared__ __align__(16) float4 pq[NN];   // (x, y, z, pad)  32KB
    __shared__ float W0s[6 * HH];
    __shared__ float sv[64][3];
    __shared__ float sdinv[64];
    int b = blockIdx.y, bN = b * NN;
    int i0 = blockIdx.x * 64;
    int tid = threadIdx.x;
    const float* pos = g_pos + (size_t)bN * 3;
    for (int j = tid; j < NN; j += 512) {
        pq[j] = make_float4(pos[j * 3 + 0], pos[j * 3 + 1], pos[j * 3 + 2],
                            padding[bN + j]);
    }
    for (int k = tid; k < 6 * HH; k += 512) W0s[k] = W0[k];
    if (tid < 192) sv[tid / 3][tid % 3] = g_vel[(bN + i0 + tid / 3) * 3 + tid % 3];
    __syncthreads();

    int warp = tid >> 5, lane = tid & 31;
    const float R2 = 0.01f;   // float32(0.1*0.1), fp32 compare like the ref

    // own 4 rows
    float xi[4], yi[4], zi[4];
    bool oki[4];
    int cnt[4], ibase[4], irow[4];
    #pragma unroll
    for (int r = 0; r < 4; r++) {
        int i = i0 + warp * 4 + r;
        float4 q = pq[i];
        xi[r] = q.x; yi[r] = q.y; zi[r] = q.z;
        oki[r] = q.w > 0.f;
        irow[r] = i;
        ibase[r] = (bN + i) * MAXN;
        cnt[r] = 0;
    }

    #pragma unroll 2
    for (int t = 0; t < NN / 32; t++) {
        int j = t * 32 + lane;
        float4 q = pq[j];
        bool padj = q.w > 0.f;
        #pragma unroll
        for (int r = 0; r < 4; r++) {
            // separate mul/add rounding — matches XLA's sub/mul/reduce-add
            float dx = __fadd_rn(q.x, -xi[r]);
            float dy = __fadd_rn(q.y, -yi[r]);
            float dz = __fadd_rn(q.z, -zi[r]);
            float d2 = __fadd_rn(__fadd_rn(__fmul_rn(dx, dx), __fmul_rn(dy, dy)),
                                 __fmul_rn(dz, dz));
            // a_hat = adj + I: diagonal always 1; self at its sorted position
            bool hit = (j == irow[r]) || (oki[r] && padj && (d2 < R2));
            unsigned m = __ballot_sync(0xffffffffu, hit);
            if (hit) {
                int off = cnt[r] + __popc(m & ((1u << lane) - 1u));
                if (off < MAXN) g_nbr[ibase[r] + off] = j;
            }
            cnt[r] += __popc(m);
        }
    }

    #pragma unroll
    for (int r = 0; r < 4; r++) {
        int c = cnt[r] > MAXN ? MAXN : cnt[r];
        if (lane == 0) {
            // XLA lowers rsqrt as 1/sqrt (correctly rounded), NOT MUFU.RSQ.
            float di = 1.0f / sqrtf((float)c);
            g_cnt[bN + irow[r]]  = c;
            g_dinv[bN + irow[r]] = di;
            sdinv[warp * 4 + r] = di;
        }
    }
    __syncthreads();

    // layer0 h for own rows (ascending-k FMA, pos then vel)
    for (int o = tid; o < 64 * HH; o += 512) {
        int r = o >> 7, col = o & 127;
        float4 q = pq[i0 + r];
        float acc = 0.f;
        acc = fmaf(q.x,      W0s[0 * HH + col], acc);
        acc = fmaf(q.y,      W0s[1 * HH + col], acc);
        acc = fmaf(q.z,      W0s[2 * HH + col], acc);
        acc = fmaf(sv[r][0], W0s[3 * HH + col], acc);
        acc = fmaf(sv[r][1], W0s[4 * HH + col], acc);
        acc = fmaf(sv[r][2], W0s[5 * HH + col], acc);
        g_ha[(size_t)(bN + i0 + r) * HH + col] = __fmul_rn(acc, sdinv[r]);
    }
}

// MLP-8 gather: up to 8 independent LDG.128 in flight, then ordered adds
// (strictly ascending t — bit-identical to the serial loop).
__device__ __forceinline__ float4 gather_row(const float* __restrict__ hin,
                                             const int* __restrict__ nb,
                                             int cnt, int bN, int lane) {
    float4 a = make_float4(0.f, 0.f, 0.f, 0.f);
    int t = 0;
    for (; t + 8 <= cnt; t += 8) {
        float4 v[8];
        #pragma unroll
        for (int u = 0; u < 8; u++)
            v[u] = __ldg((const float4*)(hin + (size_t)(bN + nb[t + u]) * HH) + lane);
        #pragma unroll
        for (int u = 0; u < 8; u++) {
            a.x = __fadd_rn(a.x, v[u].x); a.y = __fadd_rn(a.y, v[u].y);
            a.z = __fadd_rn(a.z, v[u].z); a.w = __fadd_rn(a.w, v[u].w);
        }
    }
    for (; t + 4 <= cnt; t += 4) {
        float4 v[4];
        #pragma unroll
        for (int u = 0; u < 4; u++)
            v[u] = __ldg((const float4*)(hin + (size_t)(bN + nb[t + u]) * HH) + lane);
        #pragma unroll
        for (int u = 0; u < 4; u++) {
            a.x = __fadd_rn(a.x, v[u].x); a.y = __fadd_rn(a.y, v[u].y);
            a.z = __fadd_rn(a.z, v[u].z); a.w = __fadd_rn(a.w, v[u].w);
        }
    }
    for (; t < cnt; t++) {
        float4 v = __ldg((const float4*)(hin + (size_t)(bN + nb[t]) * HH) + lane);
        a.x = __fadd_rn(a.x, v.x); a.y = __fadd_rn(a.y, v.y);
        a.z = __fadd_rn(a.z, v.z); a.w = __fadd_rn(a.w, v.w);
    }
    return a;
}

// ---------------- fused aggregate + dense GEMM, warp-local, 512 thr ---------
// Order: issue W->smem copies, then gather (W fill hides under gather
// latency), THEN the single __syncthreads, then GEMM from smem.
// src==0: g_ha -> g_hb ; src==1: g_hb -> g_ha.
__global__ __launch_bounds__(512, 2) void k_aggemm(int src,
                                                   const float* __restrict__ bias,
                                                   const float* __restrict__ W) {
    extern __shared__ __align__(16) float sm[];
    float* Ws = sm;                  // 128*128
    float* xs = sm + HH * HH;        // 64*132 (float4-aligned pitch)

    const float* hin  = src ? g_hb : g_ha;
    float*       hout = src ? g_ha : g_hb;

    int row0 = blockIdx.x * 64;
    int tid = threadIdx.x;
    int bN = (row0 / NN) * NN;       // neighbors are batch-local ids
    int warp = tid >> 5, lane = tid & 31;
    int rbase = warp * 4;

    // Issue W fill first: 4096 float4, 8 per thread. Completes under gather.
    #pragma unroll
    for (int k = 0; k < 8; k++) {
        int idx = tid + k * 512;
        ((float4*)Ws)[idx] = __ldg((const float4*)W + idx);
    }

    // Phase A (warp-local): gather own 4 rows into xs; no block sync needed.
    float4 bb = __ldg((const float4*)bias + lane);
    float dloc[4];
    #pragma unroll 1
    for (int rr = 0; rr < 4; rr++) {
        int r = rbase + rr;
        int i = row0 + r;
        float4 a = gather_row(hin, g_nbr + (size_t)i * MAXN, g_cnt[i], bN, lane);
        float di = g_dinv[i];
        dloc[rr] = di;
        float4 o;
        o.x = fmaxf(__fadd_rn(__fmul_rn(a.x, di), bb.x), 0.f);
        o.y = fmaxf(__fadd_rn(__fmul_rn(a.y, di), bb.y), 0.f);
        o.z = fmaxf(__fadd_rn(__fmul_rn(a.z, di), bb.z), 0.f);
        o.w = fmaxf(__fadd_rn(__fmul_rn(a.w, di), bb.w), 0.f);
        *(float4*)&xs[r * 132 + lane * 4] = o;
    }
    __syncthreads();                 // W + all xs ready

    // Phase B (warp-local): rows rbase..rbase+3, cols lane*4..lane*4+3.
    // k strictly ascending per accumulator — bit-identical chain.
    const float* y = xs + rbase * 132;
    float acc[4][4];
    #pragma unroll
    for (int m = 0; m < 4; m++)
        #pragma unroll
        for (int n = 0; n < 4; n++) acc[m][n] = 0.f;

    #pragma unroll 1
    for (int k0 = 0; k0 < HH; k0 += 4) {
        float4 yv0 = *(const float4*)&y[k0];
        float4 yv1 = *(const float4*)&y[132 + k0];
        float4 yv2 = *(const float4*)&y[264 + k0];
        float4 yv3 = *(const float4*)&y[396 + k0];
        #pragma unroll
        for (int kk = 0; kk < 4; kk++) {
            float4 w = *(const float4*)&Ws[(k0 + kk) * HH + lane * 4];
            float y0 = (kk == 0) ? yv0.x : (kk == 1) ? yv0.y : (kk == 2) ? yv0.z : yv0.w;
            float y1 = (kk == 0) ? yv1.x : (kk == 1) ? yv1.y : (kk == 2) ? yv1.z : yv1.w;
            float y2 = (kk == 0) ? yv2.x : (kk == 1) ? yv2.y : (kk == 2) ? yv2.z : yv2.w;
            float y3 = (kk == 0) ? yv3.x : (kk == 1) ? yv3.y : (kk == 2) ? yv3.z : yv3.w;
            acc[0][0] = fmaf(y0, w.x, acc[0][0]); acc[0][1] = fmaf(y0, w.y, acc[0][1]);
            acc[0][2] = fmaf(y0, w.z, acc[0][2]); acc[0][3] = fmaf(y0, w.w, acc[0][3]);
            acc[1][0] = fmaf(y1, w.x, acc[1][0]); acc[1][1] = fmaf(y1, w.y, acc[1][1]);
            acc[1][2] = fmaf(y1, w.z, acc[1][2]); acc[1][3] = fmaf(y1, w.w, acc[1][3]);
            acc[2][0] = fmaf(y2, w.x, acc[2][0]); acc[2][1] = fmaf(y2, w.y, acc[2][1]);
            acc[2][2] = fmaf(y2, w.z, acc[2][2]); acc[2][3] = fmaf(y2, w.w, acc[2][3]);
            acc[3][0] = fmaf(y3, w.x, acc[3][0]); acc[3][1] = fmaf(y3, w.y, acc[3][1]);
            acc[3][2] = fmaf(y3, w.z, acc[3][2]); acc[3][3] = fmaf(y3, w.w, acc[3][3]);
        }
    }

    #pragma unroll
    for (int m = 0; m < 4; m++) {
        int r = rbase + m;
        float d = dloc[m];
        float4 o;
        o.x = __fmul_rn(acc[m][0], d);
        o.y = __fmul_rn(acc[m][1], d);
        o.z = __fmul_rn(acc[m][2], d);
        o.w = __fmul_rn(acc[m][3], d);
        *(float4*)&hout[(size_t)(row0 + r) * HH + lane * 4] = o;
    }
}

// ---------------- fused aggregate + fc head + state update, warp-local -----
// Same reorder: issue Wfc fill, gather, sync, fc. Reads g_ha.
__global__ __launch_bounds__(512) void k_aggfc(const float* __restrict__ bias2,
                                               const float* __restrict__ Wfc,
                                               const float* __restrict__ bfc,
                                               const float* __restrict__ padding,
                                               float* __restrict__ out, int t) {
    __shared__ __align__(16) float xs[64 * 132];
    __shared__ float Wf[HH * 6];
    int row0 = blockIdx.x * 64;
    int tid = threadIdx.x;
    int bN = (row0 / NN) * NN;
    int warp = tid >> 5, lane = tid & 31;
    int rbase = warp * 4;

    // Issue Wfc fill (768 floats) first; completes under gather.
    for (int k = tid; k < HH * 6; k += 512) Wf[k] = __ldg(Wfc + k);

    float4 bb = __ldg((const float4*)bias2 + lane);
    #pragma unroll 1
    for (int rr = 0; rr < 4; rr++) {
        int r = rbase + rr;
        int i = row0 + r;
        float4 a = gather_row(g_ha, g_nbr + (size_t)i * MAXN, g_cnt[i], bN, lane);
        float di = g_dinv[i];
        float4 o;
        o.x = fmaxf(__fadd_rn(__fmul_rn(a.x, di), bb.x), 0.f);
        o.y = fmaxf(__fadd_rn(__fmul_rn(a.y, di), bb.y), 0.f);
        o.z = fmaxf(__fadd_rn(__fmul_rn(a.z, di), bb.z), 0.f);
        o.w = fmaxf(__fadd_rn(__fmul_rn(a.w, di), bb.w), 0.f);
        *(float4*)&xs[r * 132 + lane * 4] = o;
    }
    __syncthreads();

    // fc for own 4 rows: 24 outputs per warp (lanes 0..23).
    if (lane < 24) {
        int rr = lane / 6, c = lane % 6;
        int g = row0 + rbase + rr;
        const float* xr = xs + (rbase + rr) * 132;
        float acc = 0.f;
        #pragma unroll 8
        for (int k = 0; k < HH; k++) acc = fmaf(xr[k], Wf[k * 6 + c], acc);
        float res = __fadd_rn(acc, __ldg(bfc + c));
        res = __fmul_rn(res, padding[g]);
        if (c < 3) {
            float p = __fadd_rn(g_pos[g * 3 + c], res);
            g_pos[g * 3 + c] = p;
            int b = g / NN, n = g % NN;
            out[((size_t)(b * (TT + 1) + t + 1) * NN + n) * 3 + c] = p;
        } else {
            int a = g * 3 + (c - 3);
            g_vel[a] = __fadd_rn(g_vel[a], res);
        }
    }
}

// ---------------- launch ----------------
extern "C" void kernel_launch(void* const* d_in, const int* in_sizes, int n_in,
                              void* d_out, int out_size) {
    const float* points  = (const float*)d_in[0];
    const float* padding = (const float*)d_in[5];
    const float* W0  = (const float*)d_in[6];
    const float* b0  = (const float*)d_in[7];
    const float* W1  = (const float*)d_in[8];
    const float* b1  = (const float*)d_in[9];
    const float* W2  = (const float*)d_in[10];
    const float* b2  = (const float*)d_in[11];
    const float* Wfc = (const float*)d_in[12];
    const float* bfc = (const float*)d_in[13];
    float* out = (float*)d_out;

    const int smem_ag = (HH * HH + 64 * 132) * (int)sizeof(float);
    cudaFuncSetAttribute(k_aggemm, cudaFuncAttributeMaxDynamicSharedMemorySize,
                         smem_ag);

    const int ROWS = BD * NN;

    k_init<<<(BD * NN * 3 + 255) / 256, 256>>>(points, out);

    for (int t = 0; t < TT; t++) {
        k_adj<<<dim3(NN / 64, BD), 512>>>(padding, W0);      // -> g_ha (h0)
        k_aggemm<<<ROWS / 64, 512, smem_ag>>>(0, b0, W1);    // ha -> x -> hb
        k_aggemm<<<ROWS / 64, 512, smem_ag>>>(1, b1, W2);    // hb -> x -> ha
        k_aggfc <<<ROWS / 64, 512>>>(b2, Wfc, bfc, padding, out, t);
    }
}